// round 16
// baseline (speedup 1.0000x reference)
#include <cuda_runtime.h>
#include <cuda_bf16.h>
#include <cuda_fp16.h>
#include <cstdint>

// Problem constants
#define NB     64
#define CIN    64
#define COUT   128
#define NT     300
#define NV     25
#define TV     7500
#define TT     5
#define NTILE  125
#define NTILES 60
#define NCNT   480000
#define NTT    3840          // total GEMM tiles
#define KG_GRID 296          // persistent GEMM CTAs (2/SM)
#define NCHUNK 5120          // kA chunks = 64*8*10
#define KA_GRID 444          // persistent kA CTAs (3/SM)

// Scratch
__device__ __half g_ys[(size_t)NB * COUT * NTILES * 128];   // y fp16 [b][o][tile][128]
__device__ __half g_xg[(size_t)NTT * CIN * 136];            // xg fp16 B-tiles [tile][c][136]
__device__ float g_sum[COUT];
__device__ float g_sq[COUT];
__device__ float g_scale[COUT];
__device__ float g_shift[COUT];
__device__ __half g_whi[128 * 72];
__device__ __half g_wlo[128 * 72];

typedef unsigned long long ull;

#define A_STR  72
#define B_STR  136
#define BBYTES 17408

// ---------------- kG SMEM layout (bytes) ----------------
#define OFF_WHI   0          // 18432
#define OFF_WLO   18432      // 18432
#define OFF_B0    36864      // 17408
#define OFF_B1    54272      // 17408
#define OFF_SSUM  71680      // 512
#define OFF_SSQ   72192      // 512
#define OFF_BIAS  72704      // 512
#define KG_SMEM   73216

// ---------------- kA SMEM layout (bytes) ----------------
#define KA_XSTR   752        // floats per c-row (3008B row)
#define KA_OFF_X0 0          // 24064
#define KA_OFF_X1 24064      // 24064
#define KA_OFF_O  48128      // 48*136*2 = 13056
#define KA_OFF_ADJ 61184     // 2600
#define KA_SMEM   63784

__device__ __forceinline__ uint32_t smem_u32(const void* p) {
    uint32_t a;
    asm("{ .reg .u64 t; cvta.to.shared.u64 t, %1; cvt.u32.u64 %0, t; }" : "=r"(a) : "l"(p));
    return a;
}
__device__ __forceinline__ ull dup2(float x) {
    ull r; asm("mov.b64 %0, {%1, %1};" : "=l"(r) : "f"(x)); return r;
}
__device__ __forceinline__ void fma2(ull& d, ull a, ull b) {
    asm("fma.rn.f32x2 %0, %1, %2, %3;" : "=l"(d) : "l"(a), "l"(b), "l"(d));
}
__device__ __forceinline__ float2 unpk(ull v) {
    float2 f; asm("mov.b64 {%0, %1}, %2;" : "=f"(f.x), "=f"(f.y) : "l"(v)); return f;
}
__device__ __forceinline__ void ldm_x4(uint32_t* r, uint32_t addr) {
    asm volatile("ldmatrix.sync.aligned.m8n8.x4.shared.b16 {%0,%1,%2,%3}, [%4];"
        : "=r"(r[0]), "=r"(r[1]), "=r"(r[2]), "=r"(r[3]) : "r"(addr));
}
__device__ __forceinline__ void ldm_x4_t(uint32_t* r, uint32_t addr) {
    asm volatile("ldmatrix.sync.aligned.m8n8.x4.trans.shared.b16 {%0,%1,%2,%3}, [%4];"
        : "=r"(r[0]), "=r"(r[1]), "=r"(r[2]), "=r"(r[3]) : "r"(addr));
}
__device__ __forceinline__ void mma16816(float* d, const uint32_t* a, uint32_t b0, uint32_t b1) {
    asm volatile("mma.sync.aligned.m16n8k16.row.col.f32.f16.f16.f32 "
        "{%0,%1,%2,%3}, {%4,%5,%6,%7}, {%8,%9}, {%0,%1,%2,%3};"
        : "+f"(d[0]), "+f"(d[1]), "+f"(d[2]), "+f"(d[3])
        : "r"(a[0]), "r"(a[1]), "r"(a[2]), "r"(a[3]), "r"(b0), "r"(b1));
}
__device__ __forceinline__ uint32_t pack_half2(float a, float b) {
    __half2 h = __floats2half2_rn(a, b);
    return *(uint32_t*)&h;
}
__device__ __forceinline__ void cp_async16(uint32_t dst, const void* src) {
    asm volatile("cp.async.cg.shared.global [%0], [%1], 16;" :: "r"(dst), "l"(src));
}
__device__ __forceinline__ void cp_async8(uint32_t dst, const void* src) {
    asm volatile("cp.async.ca.shared.global [%0], [%1], 8;" :: "r"(dst), "l"(src));
}
#define CP_COMMIT() asm volatile("cp.async.commit_group;" ::: "memory")
#define CP_WAIT0()  asm volatile("cp.async.wait_group 0;" ::: "memory")
#define CP_WAIT1()  asm volatile("cp.async.wait_group 1;" ::: "memory")

// ---- kInit: zero stats + presplit W ----
__global__ void kInit(const float* __restrict__ W) {
    int idx = blockIdx.x * 256 + threadIdx.x;
    if (idx < COUT * CIN) {
        int o = idx >> 6, c = idx & 63;
        float v = W[idx];
        __half h = __float2half_rn(v);
        g_whi[o * A_STR + c] = h;
        g_wlo[o * A_STR + c] = __float2half_rn(v - __half2float(h));
    }
    if (idx < COUT) { g_sum[idx] = 0.f; g_sq[idx] = 0.f; }
}

__global__ void kNop() {}
__global__ void kNop2() {}

// ---- kA: adjacency; persistent, double-buffered, parity-packed smem access ----
__global__ void __launch_bounds__(256)
kA_adj(const float* __restrict__ x, const float* __restrict__ adj)
{
    extern __shared__ char sm[];
    const uint32_t smb = smem_u32(sm);
    __half* s_out = (__half*)(sm + KA_OFF_O);
    float*  s_adj = (float*)(sm + KA_OFF_ADJ);

    const int tid = threadIdx.x;

    for (int idx = tid; idx < 650; idx += 256) {
        int v = idx / 26, w = idx - v * 26;
        s_adj[idx] = (w < NV) ? adj[v * NV + w] : 0.f;
    }
    if (tid < 144) {
        int r = tid / 3, k = tid - r * 3;
        s_out[r * B_STR + 125 + k] = __half(0.f);
    }

    // prefetch first chunk (3000 x 8B; 16B global alignment impossible: row stride 30000B)
    {
        int t = blockIdx.x;
        int b = t / 80, rem = t - b * 80;
        int cg = rem / 10, ch = rem - cg * 10;
        const char* src = (const char*)(x + ((size_t)b * CIN + cg * 8) * TV + ch * 750);
        for (int i = tid; i < 3000; i += 256) {
            int row = i / 375, k = i - row * 375;
            cp_async8(smb + KA_OFF_X0 + row * 3008 + k * 8,
                      src + (size_t)row * 30000 + k * 8);
        }
        CP_COMMIT();
    }
    __syncthreads();

    int p = 0;
    for (int t = blockIdx.x; t < NCHUNK; t += KA_GRID) {
        const int b  = t / 80;
        const int rem = t - b * 80;
        const int cg = rem / 10;
        const int ch = rem - cg * 10;
        const int tn = t + KA_GRID;

        if (tn < NCHUNK) {
            int bn = tn / 80, remn = tn - bn * 80;
            int cgn = remn / 10, chn = remn - cgn * 10;
            const char* src = (const char*)(x + ((size_t)bn * CIN + cgn * 8) * TV + chn * 750);
            uint32_t dstb = smb + ((p ^ 1) ? KA_OFF_X1 : KA_OFF_X0);
            for (int i = tid; i < 3000; i += 256) {
                int row = i / 375, k = i - row * 375;
                cp_async8(dstb + row * 3008 + k * 8,
                          src + (size_t)row * 30000 + k * 8);
            }
            CP_COMMIT();
            CP_WAIT1();
        } else {
            CP_WAIT0();
        }
        __syncthreads();

        const float* s_x = (const float*)(sm + (p ? KA_OFF_X1 : KA_OFF_X0));
        if (tid < 240) {
            int c = tid / 30, tl30 = tid - c * 30;
            int ttl = tl30 / 5, tl = tl30 - ttl * 5;

            // x read: parity-packed float2 (12x vec + 1 scalar instead of 25 scalar)
            const float* xp = s_x + c * KA_XSTR + tl30 * NV;
            float xr[NV];
            if (tl30 & 1) {
                xr[0] = xp[0];
                #pragma unroll
                for (int q = 0; q < 12; ++q) {
                    float2 v = *(const float2*)(xp + 1 + 2 * q);
                    xr[1 + 2 * q] = v.x; xr[2 + 2 * q] = v.y;
                }
            } else {
                #pragma unroll
                for (int q = 0; q < 12; ++q) {
                    float2 v = *(const float2*)(xp + 2 * q);
                    xr[2 * q] = v.x; xr[2 * q + 1] = v.y;
                }
                xr[24] = xp[24];
            }

            ull acc[13];
            #pragma unroll
            for (int q = 0; q < 13; ++q) acc[q] = 0ull;
            #pragma unroll
            for (int v = 0; v < NV; ++v) {
                ull xv = dup2(xr[v]);
                const ull* arow = (const ull*)(s_adj + v * 26);
                #pragma unroll
                for (int q = 0; q < 13; ++q) fma2(acc[q], xv, arow[q]);
            }

            // convert to fp16 in registers
            __half h[26];
            #pragma unroll
            for (int q = 0; q < 13; ++q) {
                float2 f = unpk(acc[q]);
                h[2 * q]     = __float2half_rn(f.x);
                h[2 * q + 1] = __float2half_rn(f.y);
            }

            // output store: parity-packed half2 (12x vec + 1 scalar)
            __half* dst = s_out + (ttl * 8 + c) * B_STR + tl * NV;
            if (tl & 1) {
                dst[0] = h[0];
                #pragma unroll
                for (int q = 0; q < 12; ++q)
                    *(__half2*)(dst + 1 + 2 * q) = __halves2half2(h[1 + 2 * q], h[2 + 2 * q]);
            } else {
                #pragma unroll
                for (int q = 0; q < 12; ++q)
                    *(__half2*)(dst + 2 * q) = __halves2half2(h[2 * q], h[2 * q + 1]);
                dst[24] = h[24];
            }
        }
        __syncthreads();

        // flush: coalesced uint4
        {
            uint4* gbase = (uint4*)(g_xg + ((size_t)(b * NTILES + ch * 6) * CIN + cg * 8) * B_STR);
            const uint4* s4 = (const uint4*)s_out;
            for (int i = tid; i < 816; i += 256) {
                int lrow = i / 17, q = i - lrow * 17;
                int ttl = lrow >> 3, c = lrow & 7;
                gbase[(size_t)(ttl * CIN + c) * 17 + q] = s4[i];
            }
        }
        __syncthreads();
        p ^= 1;
    }
}

// ---- kG: persistent, double-buffered B via cp.async (proven 52us) ----
__global__ void __launch_bounds__(256, 2)
kG_gemm(const float* __restrict__ bias)
{
    extern __shared__ char sm[];
    const uint32_t smb = smem_u32(sm);
    float* s_sum  = (float*)(sm + OFF_SSUM);
    float* s_sq   = (float*)(sm + OFF_SSQ);
    float* s_bias = (float*)(sm + OFF_BIAS);

    const int tid = threadIdx.x;
    const int wid = tid >> 5;
    const int lid = tid & 31;

    #pragma unroll
    for (int k = 0; k < 5; ++k) {
        int i = tid + k * 256;
        if (i < 1152) {
            cp_async16(smb + OFF_WHI + i * 16, (const char*)g_whi + i * 16);
            cp_async16(smb + OFF_WLO + i * 16, (const char*)g_wlo + i * 16);
        }
    }
    {
        const char* src = (const char*)(g_xg + (size_t)blockIdx.x * (CIN * B_STR));
        #pragma unroll
        for (int k = 0; k < 5; ++k) {
            int i = tid + k * 256;
            if (i < 1088) cp_async16(smb + OFF_B0 + i * 16, src + i * 16);
        }
    }
    CP_COMMIT();
    if (tid < COUT) { s_bias[tid] = bias[tid]; s_sum[tid] = 0.f; s_sq[tid] = 0.f; }
    CP_WAIT0();
    __syncthreads();

    const int warpM = wid >> 1;
    const int warpN = wid & 1;
    const int mbase = warpM * 32;
    const int nbase = warpN * 64;
    const int lrow  = lid & 15;
    const int lcol8 = (lid >> 4) * 8;
    const int qrow  = lid >> 2;
    const int qcol  = (lid & 3) * 2;

    float tsum[2][2] = {{0.f, 0.f}, {0.f, 0.f}};
    float tsq[2][2]  = {{0.f, 0.f}, {0.f, 0.f}};

    int p = 0;
    for (int t = blockIdx.x; t < NTT; t += KG_GRID) {
        const int b  = t / NTILES;
        const int tt = t - b * NTILES;
        const int tn = t + KG_GRID;

        if (tn < NTT) {
            const char* src = (const char*)(g_xg + (size_t)tn * (CIN * B_STR));
            uint32_t dstb = smb + OFF_B0 + (p ^ 1) * BBYTES;
            #pragma unroll
            for (int k = 0; k < 5; ++k) {
                int i = tid + k * 256;
                if (i < 1088) cp_async16(dstb + i * 16, src + i * 16);
            }
            CP_COMMIT();
        }

        const uint32_t offB = OFF_B0 + p * BBYTES;
        float acc[2][8][4];
        #pragma unroll
        for (int mt = 0; mt < 2; ++mt)
            #pragma unroll
            for (int nt = 0; nt < 8; ++nt)
                #pragma unroll
                for (int e = 0; e < 4; ++e) acc[mt][nt][e] = 0.f;

        #pragma unroll
        for (int ks = 0; ks < 4; ++ks) {
            uint32_t ahi[2][4], alo[2][4];
            #pragma unroll
            for (int mt = 0; mt < 2; ++mt) {
                uint32_t arow = mbase + mt * 16 + lrow;
                uint32_t acolb = ks * 16 + lcol8;
                ldm_x4(ahi[mt], smb + OFF_WHI + (arow * A_STR + acolb) * 2);
                ldm_x4(alo[mt], smb + OFF_WLO + (arow * A_STR + acolb) * 2);
            }
            uint32_t bF[4][4];
            #pragma unroll
            for (int q = 0; q < 4; ++q) {
                uint32_t brow = ks * 16 + lrow;
                uint32_t bcol = nbase + q * 16 + lcol8;
                ldm_x4_t(bF[q], smb + offB + (brow * B_STR + bcol) * 2);
            }
            #pragma unroll
            for (int mt = 0; mt < 2; ++mt)
                #pragma unroll
                for (int q = 0; q < 4; ++q)
                    #pragma unroll
                    for (int h = 0; h < 2; ++h) {
                        float* d = acc[mt][q * 2 + h];
                        uint32_t b0 = bF[q][h * 2], b1 = bF[q][h * 2 + 1];
                        mma16816(d, ahi[mt], b0, b1);
                        mma16816(d, alo[mt], b0, b1);
                    }
        }

        #pragma unroll
        for (int mt = 0; mt < 2; ++mt) {
            int r0 = mbase + mt * 16 + qrow;
            float b0 = s_bias[r0], b1 = s_bias[r0 + 8];
            #pragma unroll
            for (int nt = 0; nt < 8; ++nt) {
                int j0 = nbase + nt * 8 + qcol;
                float* d = acc[mt][nt];
                d[0] += b0; d[1] += b0; d[2] += b1; d[3] += b1;
                if (j0 < NTILE)     { tsum[mt][0] += d[0]; tsq[mt][0] += d[0] * d[0];
                                      tsum[mt][1] += d[2]; tsq[mt][1] += d[2] * d[2]; }
                if (j0 + 1 < NTILE) { tsum[mt][0] += d[1]; tsq[mt][0] += d[1] * d[1];
                                      tsum[mt][1] += d[3]; tsq[mt][1] += d[3] * d[3]; }
            }
        }
        __syncthreads();

        uint32_t* stage = (uint32_t*)(sm + OFF_B0 + p * BBYTES);
        uint4* stage4 = (uint4*)(sm + OFF_B0 + p * BBYTES);
        const size_t yb = (size_t)b * COUT * (NTILES * 128) + (size_t)tt * 128;

        if (wid < 4) {
            #pragma unroll
            for (int mt = 0; mt < 2; ++mt) {
                int r0 = mbase + mt * 16 + qrow;
                #pragma unroll
                for (int nt = 0; nt < 8; ++nt) {
                    float* d = acc[mt][nt];
                    int j0 = nbase + nt * 8 + qcol;
                    stage[(r0 * B_STR + j0) >> 1]       = pack_half2(d[0], d[1]);
                    stage[((r0 + 8) * B_STR + j0) >> 1] = pack_half2(d[2], d[3]);
                }
            }
        }
        __syncthreads();
        #pragma unroll
        for (int k = 0; k < 4; ++k) {
            int idx = tid + k * 256;
            int row = idx >> 4, q = idx & 15;
            uint4* dst = (uint4*)(g_ys + yb + (size_t)row * (NTILES * 128));
            dst[q] = stage4[row * 17 + q];
        }
        __syncthreads();

        if (wid >= 4) {
            #pragma unroll
            for (int mt = 0; mt < 2; ++mt) {
                int r0 = mbase + mt * 16 + qrow - 64;
                #pragma unroll
                for (int nt = 0; nt < 8; ++nt) {
                    float* d = acc[mt][nt];
                    int j0 = nbase + nt * 8 + qcol;
                    stage[(r0 * B_STR + j0) >> 1]       = pack_half2(d[0], d[1]);
                    stage[((r0 + 8) * B_STR + j0) >> 1] = pack_half2(d[2], d[3]);
                }
            }
        }
        __syncthreads();
        #pragma unroll
        for (int k = 0; k < 4; ++k) {
            int idx = tid + k * 256;
            int row = idx >> 4, q = idx & 15;
            uint4* dst = (uint4*)(g_ys + yb + (size_t)(row + 64) * (NTILES * 128));
            dst[q] = stage4[row * 17 + q];
        }
        if (tn < NTT) CP_WAIT0();
        __syncthreads();
        p ^= 1;
    }

    #pragma unroll
    for (int mt = 0; mt < 2; ++mt)
        #pragma unroll
        for (int rr = 0; rr < 2; ++rr) {
            float s = tsum[mt][rr], q = tsq[mt][rr];
            s += __shfl_xor_sync(0xffffffffu, s, 1); q += __shfl_xor_sync(0xffffffffu, q, 1);
            s += __shfl_xor_sync(0xffffffffu, s, 2); q += __shfl_xor_sync(0xffffffffu, q, 2);
            if ((lid & 3) == 0) {
                int o = mbase + mt * 16 + qrow + rr * 8;
                atomicAdd(&s_sum[o], s);
                atomicAdd(&s_sq[o], q);
            }
        }
    __syncthreads();
    if (tid < COUT) {
        atomicAdd(&g_sum[tid], s_sum[tid]);
        atomicAdd(&g_sq[tid], s_sq[tid]);
    }
}

// ---- k2: per-channel scale/shift (once) ----
__global__ void k2_finalize(const float* __restrict__ gamma, const float* __restrict__ beta) {
    int i = threadIdx.x;
    float mean = g_sum[i] * (1.0f / NCNT);
    float var  = g_sq[i]  * (1.0f / NCNT) - mean * mean;
    float sc   = gamma[i] * rsqrtf(var + 1e-5f);
    g_scale[i] = sc;
    g_shift[i] = beta[i] - mean * sc;
}

// ---- k3: normalize + relu ----
__global__ void k3_norm(float* __restrict__ out) {
    unsigned int idx = blockIdx.x * 256u + threadIdx.x;
    unsigned int e = idx * 4u;
    if (e >= 61440000u) return;
    unsigned int row = e / TV;          // b*128+o
    int o = row & 127;
    unsigned int g = e - row * TV;
    float sc = g_scale[o], sh = g_shift[o];
    const __half* yrow = g_ys + (size_t)row * (NTILES * 128);
    float4 r;
    {
        unsigned int gg = g;     unsigned int t0 = gg / NTILE;
        r.x = fmaxf(fmaf(__half2float(yrow[t0 * 128 + (gg - t0 * NTILE)]), sc, sh), 0.f);
    }
    {
        unsigned int gg = g + 1; unsigned int t0 = gg / NTILE;
        r.y = fmaxf(fmaf(__half2float(yrow[t0 * 128 + (gg - t0 * NTILE)]), sc, sh), 0.f);
    }
    {
        unsigned int gg = g + 2; unsigned int t0 = gg / NTILE;
        r.z = fmaxf(fmaf(__half2float(yrow[t0 * 128 + (gg - t0 * NTILE)]), sc, sh), 0.f);
    }
    {
        unsigned int gg = g + 3; unsigned int t0 = gg / NTILE;
        r.w = fmaxf(fmaf(__half2float(yrow[t0 * 128 + (gg - t0 * NTILE)]), sc, sh), 0.f);
    }
    *(float4*)(out + e) = r;
}

extern "C" void kernel_launch(void* const* d_in, const int* in_sizes, int n_in,
                              void* d_out, int out_size)
{
    (void)in_sizes; (void)n_in; (void)out_size;
    const float* x     = (const float*)d_in[0];
    const float* adj   = (const float*)d_in[1];
    const float* W     = (const float*)d_in[2];
    const float* bias  = (const float*)d_in[3];
    const float* gamma = (const float*)d_in[4];
    const float* beta  = (const float*)d_in[5];
    float* out = (float*)d_out;

    cudaFuncSetAttribute(kA_adj,  cudaFuncAttributeMaxDynamicSharedMemorySize, KA_SMEM);
    cudaFuncSetAttribute(kG_gemm, cudaFuncAttributeMaxDynamicSharedMemorySize, KG_SMEM);

    kInit<<<32, 256>>>(W);                         // 1
    kNop<<<1, 32>>>();                             // 2
    kNop2<<<1, 32>>>();                            // 3
    kA_adj<<<KA_GRID, 256, KA_SMEM>>>(x, adj);     // 4  <- ncu capture slot
    kG_gemm<<<KG_GRID, 256, KG_SMEM>>>(bias);      // 5
    k2_finalize<<<1, 128>>>(gamma, beta);          // 6
    k3_norm<<<60000, 256>>>(out);                  // 7
}

// round 17
// speedup vs baseline: 1.0914x; 1.0914x over previous
#include <cuda_runtime.h>
#include <cuda_bf16.h>
#include <cuda_fp16.h>
#include <cstdint>

// Problem constants
#define NB     64
#define CIN    64
#define COUT   128
#define NT     300
#define NV     25
#define TV     7500
#define TT     5
#define NTILE  125
#define NTILES 60
#define NCNT   480000
#define NTT    3840          // total GEMM tiles
#define KG_GRID 296          // persistent GEMM CTAs (2/SM)
#define NCHUNK 5120          // kA chunks = 64*8*10
#define KA_GRID 444          // persistent kA CTAs (3/SM)

// Scratch
__device__ __half g_ys[(size_t)NB * COUT * NTILES * 128];   // y fp16 [b][o][tile][128]
__device__ __half g_xg[(size_t)NTT * CIN * 136];            // xg fp16 B-tiles [tile][c][136]
__device__ float g_sum[COUT];
__device__ float g_sq[COUT];
__device__ float g_scale[COUT];
__device__ float g_shift[COUT];
__device__ __half g_whi[128 * 72];
__device__ __half g_wlo[128 * 72];

typedef unsigned long long ull;

#define A_STR  72
#define B_STR  136
#define BBYTES 17408

// ---------------- kG SMEM layout (bytes) ----------------
#define OFF_WHI   0          // 18432
#define OFF_WLO   18432      // 18432
#define OFF_B0    36864      // 17408
#define OFF_B1    54272      // 17408
#define OFF_SSUM  71680      // 512
#define OFF_SSQ   72192      // 512
#define OFF_BIAS  72704      // 512
#define KG_SMEM   73216

// ---------------- kA SMEM layout (bytes) ----------------
#define KA_XSTR   752        // floats per c-row (3008B row)
#define KA_OFF_X0 0          // 24064
#define KA_OFF_X1 24064      // 24064
#define KA_OFF_O  48128      // 48*136*2 = 13056
#define KA_OFF_ADJ 61184     // 2600
#define KA_SMEM   63784

__device__ __forceinline__ uint32_t smem_u32(const void* p) {
    uint32_t a;
    asm("{ .reg .u64 t; cvta.to.shared.u64 t, %1; cvt.u32.u64 %0, t; }" : "=r"(a) : "l"(p));
    return a;
}
__device__ __forceinline__ ull dup2(float x) {
    ull r; asm("mov.b64 %0, {%1, %1};" : "=l"(r) : "f"(x)); return r;
}
__device__ __forceinline__ void fma2(ull& d, ull a, ull b) {
    asm("fma.rn.f32x2 %0, %1, %2, %3;" : "=l"(d) : "l"(a), "l"(b), "l"(d));
}
__device__ __forceinline__ float2 unpk(ull v) {
    float2 f; asm("mov.b64 {%0, %1}, %2;" : "=f"(f.x), "=f"(f.y) : "l"(v)); return f;
}
__device__ __forceinline__ void ldm_x4(uint32_t* r, uint32_t addr) {
    asm volatile("ldmatrix.sync.aligned.m8n8.x4.shared.b16 {%0,%1,%2,%3}, [%4];"
        : "=r"(r[0]), "=r"(r[1]), "=r"(r[2]), "=r"(r[3]) : "r"(addr));
}
__device__ __forceinline__ void ldm_x4_t(uint32_t* r, uint32_t addr) {
    asm volatile("ldmatrix.sync.aligned.m8n8.x4.trans.shared.b16 {%0,%1,%2,%3}, [%4];"
        : "=r"(r[0]), "=r"(r[1]), "=r"(r[2]), "=r"(r[3]) : "r"(addr));
}
__device__ __forceinline__ void mma16816(float* d, const uint32_t* a, uint32_t b0, uint32_t b1) {
    asm volatile("mma.sync.aligned.m16n8k16.row.col.f32.f16.f16.f32 "
        "{%0,%1,%2,%3}, {%4,%5,%6,%7}, {%8,%9}, {%0,%1,%2,%3};"
        : "+f"(d[0]), "+f"(d[1]), "+f"(d[2]), "+f"(d[3])
        : "r"(a[0]), "r"(a[1]), "r"(a[2]), "r"(a[3]), "r"(b0), "r"(b1));
}
__device__ __forceinline__ uint32_t pack_half2(float a, float b) {
    __half2 h = __floats2half2_rn(a, b);
    return *(uint32_t*)&h;
}
__device__ __forceinline__ void cp_async16(uint32_t dst, const void* src) {
    asm volatile("cp.async.cg.shared.global [%0], [%1], 16;" :: "r"(dst), "l"(src));
}
__device__ __forceinline__ void cp_async8(uint32_t dst, const void* src) {
    asm volatile("cp.async.ca.shared.global [%0], [%1], 8;" :: "r"(dst), "l"(src));
}
#define CP_COMMIT() asm volatile("cp.async.commit_group;" ::: "memory")
#define CP_WAIT0()  asm volatile("cp.async.wait_group 0;" ::: "memory")
#define CP_WAIT1()  asm volatile("cp.async.wait_group 1;" ::: "memory")

// ---- kInit: zero stats + presplit W ----
__global__ void kInit(const float* __restrict__ W) {
    int idx = blockIdx.x * 256 + threadIdx.x;
    if (idx < COUT * CIN) {
        int o = idx >> 6, c = idx & 63;
        float v = W[idx];
        __half h = __float2half_rn(v);
        g_whi[o * A_STR + c] = h;
        g_wlo[o * A_STR + c] = __float2half_rn(v - __half2float(h));
    }
    if (idx < COUT) { g_sum[idx] = 0.f; g_sq[idx] = 0.f; }
}

__global__ void kNop() {}
__global__ void kNop2() {}

// ---- kA: adjacency; persistent, double-buffered; 2 tasks/thread to
//      amortize the 325 broadcast adj LDS.64 per task (the measured binder) ----
__global__ void __launch_bounds__(256, 3)
kA_adj(const float* __restrict__ x, const float* __restrict__ adj)
{
    extern __shared__ char sm[];
    const uint32_t smb = smem_u32(sm);
    __half* s_out = (__half*)(sm + KA_OFF_O);
    float*  s_adj = (float*)(sm + KA_OFF_ADJ);

    const int tid = threadIdx.x;

    for (int idx = tid; idx < 650; idx += 256) {
        int v = idx / 26, w = idx - v * 26;
        s_adj[idx] = (w < NV) ? adj[v * NV + w] : 0.f;
    }
    if (tid < 144) {
        int r = tid / 3, k = tid - r * 3;
        s_out[r * B_STR + 125 + k] = __half(0.f);
    }

    // prefetch first chunk (3000 x 8B; 16B global alignment impossible: row stride 30000B)
    {
        int t = blockIdx.x;
        int b = t / 80, rem = t - b * 80;
        int cg = rem / 10, ch = rem - cg * 10;
        const char* src = (const char*)(x + ((size_t)b * CIN + cg * 8) * TV + ch * 750);
        for (int i = tid; i < 3000; i += 256) {
            int row = i / 375, k = i - row * 375;
            cp_async8(smb + KA_OFF_X0 + row * 3008 + k * 8,
                      src + (size_t)row * 30000 + k * 8);
        }
        CP_COMMIT();
    }
    __syncthreads();

    int p = 0;
    for (int t = blockIdx.x; t < NCHUNK; t += KA_GRID) {
        const int b  = t / 80;
        const int rem = t - b * 80;
        const int cg = rem / 10;
        const int ch = rem - cg * 10;
        const int tn = t + KA_GRID;

        if (tn < NCHUNK) {
            int bn = tn / 80, remn = tn - bn * 80;
            int cgn = remn / 10, chn = remn - cgn * 10;
            const char* src = (const char*)(x + ((size_t)bn * CIN + cgn * 8) * TV + chn * 750);
            uint32_t dstb = smb + ((p ^ 1) ? KA_OFF_X1 : KA_OFF_X0);
            for (int i = tid; i < 3000; i += 256) {
                int row = i / 375, k = i - row * 375;
                cp_async8(dstb + row * 3008 + k * 8,
                          src + (size_t)row * 30000 + k * 8);
            }
            CP_COMMIT();
            CP_WAIT1();
        } else {
            CP_WAIT0();
        }
        __syncthreads();

        // compute: 120 threads, each owns tasks (c, tl30) and (c+4, tl30)
        const float* s_x = (const float*)(sm + (p ? KA_OFF_X1 : KA_OFF_X0));
        if (tid < 120) {
            int c = tid / 30, tl30 = tid - c * 30;   // c in 0..3
            int ttl = tl30 / 5, tl = tl30 - ttl * 5;
            const float* xpA = s_x + c * KA_XSTR + tl30 * NV;
            const float* xpB = xpA + 4 * KA_XSTR;

            ull accA[13], accB[13];
            #pragma unroll
            for (int q = 0; q < 13; ++q) { accA[q] = 0ull; accB[q] = 0ull; }

            #pragma unroll
            for (int v = 0; v < NV; ++v) {
                ull xa = dup2(xpA[v]);
                ull xb = dup2(xpB[v]);
                const ull* arow = (const ull*)(s_adj + v * 26);
                #pragma unroll
                for (int q = 0; q < 13; ++q) {
                    ull a = arow[q];                 // ONE broadcast load, TWO fma2
                    fma2(accA[q], xa, a);
                    fma2(accB[q], xb, a);
                }
            }

            __half* dstA = s_out + (ttl * 8 + c) * B_STR + tl * NV;
            __half* dstB = dstA + 4 * B_STR;
            #pragma unroll
            for (int q = 0; q < 13; ++q) {
                float2 fa = unpk(accA[q]);
                float2 fb = unpk(accB[q]);
                int w = 2 * q;
                dstA[w] = __float2half_rn(fa.x);
                dstB[w] = __float2half_rn(fb.x);
                if (w + 1 < NV) {
                    dstA[w + 1] = __float2half_rn(fa.y);
                    dstB[w + 1] = __float2half_rn(fb.y);
                }
            }
        }
        __syncthreads();

        // flush: coalesced uint4
        {
            uint4* gbase = (uint4*)(g_xg + ((size_t)(b * NTILES + ch * 6) * CIN + cg * 8) * B_STR);
            const uint4* s4 = (const uint4*)s_out;
            for (int i = tid; i < 816; i += 256) {
                int lrow = i / 17, q = i - lrow * 17;
                int ttl = lrow >> 3, c = lrow & 7;
                gbase[(size_t)(ttl * CIN + c) * 17 + q] = s4[i];
            }
        }
        __syncthreads();
        p ^= 1;
    }
}

// ---- kG: persistent, double-buffered B via cp.async (proven 52us) ----
__global__ void __launch_bounds__(256, 2)
kG_gemm(const float* __restrict__ bias)
{
    extern __shared__ char sm[];
    const uint32_t smb = smem_u32(sm);
    float* s_sum  = (float*)(sm + OFF_SSUM);
    float* s_sq   = (float*)(sm + OFF_SSQ);
    float* s_bias = (float*)(sm + OFF_BIAS);

    const int tid = threadIdx.x;
    const int wid = tid >> 5;
    const int lid = tid & 31;

    #pragma unroll
    for (int k = 0; k < 5; ++k) {
        int i = tid + k * 256;
        if (i < 1152) {
            cp_async16(smb + OFF_WHI + i * 16, (const char*)g_whi + i * 16);
            cp_async16(smb + OFF_WLO + i * 16, (const char*)g_wlo + i * 16);
        }
    }
    {
        const char* src = (const char*)(g_xg + (size_t)blockIdx.x * (CIN * B_STR));
        #pragma unroll
        for (int k = 0; k < 5; ++k) {
            int i = tid + k * 256;
            if (i < 1088) cp_async16(smb + OFF_B0 + i * 16, src + i * 16);
        }
    }
    CP_COMMIT();
    if (tid < COUT) { s_bias[tid] = bias[tid]; s_sum[tid] = 0.f; s_sq[tid] = 0.f; }
    CP_WAIT0();
    __syncthreads();

    const int warpM = wid >> 1;
    const int warpN = wid & 1;
    const int mbase = warpM * 32;
    const int nbase = warpN * 64;
    const int lrow  = lid & 15;
    const int lcol8 = (lid >> 4) * 8;
    const int qrow  = lid >> 2;
    const int qcol  = (lid & 3) * 2;

    float tsum[2][2] = {{0.f, 0.f}, {0.f, 0.f}};
    float tsq[2][2]  = {{0.f, 0.f}, {0.f, 0.f}};

    int p = 0;
    for (int t = blockIdx.x; t < NTT; t += KG_GRID) {
        const int b  = t / NTILES;
        const int tt = t - b * NTILES;
        const int tn = t + KG_GRID;

        if (tn < NTT) {
            const char* src = (const char*)(g_xg + (size_t)tn * (CIN * B_STR));
            uint32_t dstb = smb + OFF_B0 + (p ^ 1) * BBYTES;
            #pragma unroll
            for (int k = 0; k < 5; ++k) {
                int i = tid + k * 256;
                if (i < 1088) cp_async16(dstb + i * 16, src + i * 16);
            }
            CP_COMMIT();
        }

        const uint32_t offB = OFF_B0 + p * BBYTES;
        float acc[2][8][4];
        #pragma unroll
        for (int mt = 0; mt < 2; ++mt)
            #pragma unroll
            for (int nt = 0; nt < 8; ++nt)
                #pragma unroll
                for (int e = 0; e < 4; ++e) acc[mt][nt][e] = 0.f;

        #pragma unroll
        for (int ks = 0; ks < 4; ++ks) {
            uint32_t ahi[2][4], alo[2][4];
            #pragma unroll
            for (int mt = 0; mt < 2; ++mt) {
                uint32_t arow = mbase + mt * 16 + lrow;
                uint32_t acolb = ks * 16 + lcol8;
                ldm_x4(ahi[mt], smb + OFF_WHI + (arow * A_STR + acolb) * 2);
                ldm_x4(alo[mt], smb + OFF_WLO + (arow * A_STR + acolb) * 2);
            }
            uint32_t bF[4][4];
            #pragma unroll
            for (int q = 0; q < 4; ++q) {
                uint32_t brow = ks * 16 + lrow;
                uint32_t bcol = nbase + q * 16 + lcol8;
                ldm_x4_t(bF[q], smb + offB + (brow * B_STR + bcol) * 2);
            }
            #pragma unroll
            for (int mt = 0; mt < 2; ++mt)
                #pragma unroll
                for (int q = 0; q < 4; ++q)
                    #pragma unroll
                    for (int h = 0; h < 2; ++h) {
                        float* d = acc[mt][q * 2 + h];
                        uint32_t b0 = bF[q][h * 2], b1 = bF[q][h * 2 + 1];
                        mma16816(d, ahi[mt], b0, b1);
                        mma16816(d, alo[mt], b0, b1);
                    }
        }

        #pragma unroll
        for (int mt = 0; mt < 2; ++mt) {
            int r0 = mbase + mt * 16 + qrow;
            float b0 = s_bias[r0], b1 = s_bias[r0 + 8];
            #pragma unroll
            for (int nt = 0; nt < 8; ++nt) {
                int j0 = nbase + nt * 8 + qcol;
                float* d = acc[mt][nt];
                d[0] += b0; d[1] += b0; d[2] += b1; d[3] += b1;
                if (j0 < NTILE)     { tsum[mt][0] += d[0]; tsq[mt][0] += d[0] * d[0];
                                      tsum[mt][1] += d[2]; tsq[mt][1] += d[2] * d[2]; }
                if (j0 + 1 < NTILE) { tsum[mt][0] += d[1]; tsq[mt][0] += d[1] * d[1];
                                      tsum[mt][1] += d[3]; tsq[mt][1] += d[3] * d[3]; }
            }
        }
        __syncthreads();

        uint32_t* stage = (uint32_t*)(sm + OFF_B0 + p * BBYTES);
        uint4* stage4 = (uint4*)(sm + OFF_B0 + p * BBYTES);
        const size_t yb = (size_t)b * COUT * (NTILES * 128) + (size_t)tt * 128;

        if (wid < 4) {
            #pragma unroll
            for (int mt = 0; mt < 2; ++mt) {
                int r0 = mbase + mt * 16 + qrow;
                #pragma unroll
                for (int nt = 0; nt < 8; ++nt) {
                    float* d = acc[mt][nt];
                    int j0 = nbase + nt * 8 + qcol;
                    stage[(r0 * B_STR + j0) >> 1]       = pack_half2(d[0], d[1]);
                    stage[((r0 + 8) * B_STR + j0) >> 1] = pack_half2(d[2], d[3]);
                }
            }
        }
        __syncthreads();
        #pragma unroll
        for (int k = 0; k < 4; ++k) {
            int idx = tid + k * 256;
            int row = idx >> 4, q = idx & 15;
            uint4* dst = (uint4*)(g_ys + yb + (size_t)row * (NTILES * 128));
            dst[q] = stage4[row * 17 + q];
        }
        __syncthreads();

        if (wid >= 4) {
            #pragma unroll
            for (int mt = 0; mt < 2; ++mt) {
                int r0 = mbase + mt * 16 + qrow - 64;
                #pragma unroll
                for (int nt = 0; nt < 8; ++nt) {
                    float* d = acc[mt][nt];
                    int j0 = nbase + nt * 8 + qcol;
                    stage[(r0 * B_STR + j0) >> 1]       = pack_half2(d[0], d[1]);
                    stage[((r0 + 8) * B_STR + j0) >> 1] = pack_half2(d[2], d[3]);
                }
            }
        }
        __syncthreads();
        #pragma unroll
        for (int k = 0; k < 4; ++k) {
            int idx = tid + k * 256;
            int row = idx >> 4, q = idx & 15;
            uint4* dst = (uint4*)(g_ys + yb + (size_t)(row + 64) * (NTILES * 128));
            dst[q] = stage4[row * 17 + q];
        }
        if (tn < NTT) CP_WAIT0();
        __syncthreads();
        p ^= 1;
    }

    #pragma unroll
    for (int mt = 0; mt < 2; ++mt)
        #pragma unroll
        for (int rr = 0; rr < 2; ++rr) {
            float s = tsum[mt][rr], q = tsq[mt][rr];
            s += __shfl_xor_sync(0xffffffffu, s, 1); q += __shfl_xor_sync(0xffffffffu, q, 1);
            s += __shfl_xor_sync(0xffffffffu, s, 2); q += __shfl_xor_sync(0xffffffffu, q, 2);
            if ((lid & 3) == 0) {
                int o = mbase + mt * 16 + qrow + rr * 8;
                atomicAdd(&s_sum[o], s);
                atomicAdd(&s_sq[o], q);
            }
        }
    __syncthreads();
    if (tid < COUT) {
        atomicAdd(&g_sum[tid], s_sum[tid]);
        atomicAdd(&g_sq[tid], s_sq[tid]);
    }
}

// ---- k2: per-channel scale/shift (once) ----
__global__ void k2_finalize(const float* __restrict__ gamma, const float* __restrict__ beta) {
    int i = threadIdx.x;
    float mean = g_sum[i] * (1.0f / NCNT);
    float var  = g_sq[i]  * (1.0f / NCNT) - mean * mean;
    float sc   = gamma[i] * rsqrtf(var + 1e-5f);
    g_scale[i] = sc;
    g_shift[i] = beta[i] - mean * sc;
}

// ---- k3: normalize + relu ----
__global__ void k3_norm(float* __restrict__ out) {
    unsigned int idx = blockIdx.x * 256u + threadIdx.x;
    unsigned int e = idx * 4u;
    if (e >= 61440000u) return;
    unsigned int row = e / TV;          // b*128+o
    int o = row & 127;
    unsigned int g = e - row * TV;
    float sc = g_scale[o], sh = g_shift[o];
    const __half* yrow = g_ys + (size_t)row * (NTILES * 128);
    float4 r;
    {
        unsigned int gg = g;     unsigned int t0 = gg / NTILE;
        r.x = fmaxf(fmaf(__half2float(yrow[t0 * 128 + (gg - t0 * NTILE)]), sc, sh), 0.f);
    }
    {
        unsigned int gg = g + 1; unsigned int t0 = gg / NTILE;
        r.y = fmaxf(fmaf(__half2float(yrow[t0 * 128 + (gg - t0 * NTILE)]), sc, sh), 0.f);
    }
    {
        unsigned int gg = g + 2; unsigned int t0 = gg / NTILE;
        r.z = fmaxf(fmaf(__half2float(yrow[t0 * 128 + (gg - t0 * NTILE)]), sc, sh), 0.f);
    }
    {
        unsigned int gg = g + 3; unsigned int t0 = gg / NTILE;
        r.w = fmaxf(fmaf(__half2float(yrow[t0 * 128 + (gg - t0 * NTILE)]), sc, sh), 0.f);
    }
    *(float4*)(out + e) = r;
}

extern "C" void kernel_launch(void* const* d_in, const int* in_sizes, int n_in,
                              void* d_out, int out_size)
{
    (void)in_sizes; (void)n_in; (void)out_size;
    const float* x     = (const float*)d_in[0];
    const float* adj   = (const float*)d_in[1];
    const float* W     = (const float*)d_in[2];
    const float* bias  = (const float*)d_in[3];
    const float* gamma = (const float*)d_in[4];
    const float* beta  = (const float*)d_in[5];
    float* out = (float*)d_out;

    cudaFuncSetAttribute(kA_adj,  cudaFuncAttributeMaxDynamicSharedMemorySize, KA_SMEM);
    cudaFuncSetAttribute(kG_gemm, cudaFuncAttributeMaxDynamicSharedMemorySize, KG_SMEM);

    kInit<<<32, 256>>>(W);                         // 1
    kNop<<<1, 32>>>();                             // 2
    kNop2<<<1, 32>>>();                            // 3
    kA_adj<<<KA_GRID, 256, KA_SMEM>>>(x, adj);     // 4  <- ncu capture slot
    kG_gemm<<<KG_GRID, 256, KG_SMEM>>>(bias);      // 5
    k2_finalize<<<1, 128>>>(gamma, beta);          // 6
    k3_norm<<<60000, 256>>>(out);                  // 7
}